// round 4
// baseline (speedup 1.0000x reference)
#include <cuda_runtime.h>
#include <math.h>

#define EPS 1e-9f

#define BATCH   64
#define HW1     64
#define HW2     28
#define NROUTES 6272
#define NCAPS   10
#define ODIM    16
#define JDIM    8

#define RBLOCKS 392
#define NPER    16
#define WROW    132

typedef unsigned long long u64;

__device__ float g_h[(size_t)BATCH*64*HW1*HW1];    // conv1 out
__device__ float g_u[(size_t)BATCH*NROUTES*JDIM];  // primary caps
__device__ float g_v[BATCH*NCAPS*ODIM];            // v0, then v0+v1
__device__ float g_s[BATCH*NCAPS*ODIM];            // routing accumulator

// ---------- packed fp32x2 helpers ----------
__device__ __forceinline__ u64 pack2(float x) {
    u64 r; asm("mov.b64 %0, {%1, %1};" : "=l"(r) : "f"(x)); return r;
}
__device__ __forceinline__ void ffma2(u64& d, u64 a, u64 b) {
    asm("fma.rn.f32x2 %0, %1, %2, %0;" : "+l"(d) : "l"(a), "l"(b));
}
__device__ __forceinline__ float2 unpack2(u64 a) {
    float2 f; asm("mov.b64 {%0, %1}, %2;" : "=f"(f.x), "=f"(f.y) : "l"(a)); return f;
}

// ============================================================
__global__ void zero_s_kernel() {
    int i = blockIdx.x * 256 + threadIdx.x;
    if (i < BATCH*NCAPS*ODIM) g_s[i] = 0.f;
}

// ============================================================
// conv1: (64,1,64,64) -> (64,64,64,64), k5 pad2 + bias + relu
// ============================================================
__global__ __launch_bounds__(256) void conv1_kernel(
    const float* __restrict__ x, const float* __restrict__ w,
    const float* __restrict__ bias)
{
    __shared__ float xs[20][20];
    __shared__ float ws[64*25];
    __shared__ float bs[64];
    int b   = blockIdx.z;
    int ty0 = blockIdx.y * 16, tx0 = blockIdx.x * 16;
    int tid = threadIdx.y * 16 + threadIdx.x;

    for (int i = tid; i < 64*25; i += 256) ws[i] = w[i];
    if (tid < 64) bs[tid] = bias[tid];

    const float* xb = x + (size_t)b * HW1 * HW1;
    for (int i = tid; i < 400; i += 256) {
        int r = i / 20, c = i % 20;
        int gy = ty0 + r - 2, gx = tx0 + c - 2;
        float v = 0.f;
        if (gy >= 0 && gy < HW1 && gx >= 0 && gx < HW1) v = xb[gy*HW1 + gx];
        xs[r][c] = v;
    }
    __syncthreads();

    int ty = threadIdx.y, tx = threadIdx.x;
    float in[25];
#pragma unroll
    for (int kh = 0; kh < 5; kh++)
#pragma unroll
        for (int kw = 0; kw < 5; kw++)
            in[kh*5+kw] = xs[ty+kh][tx+kw];

    int y = ty0 + ty, xc = tx0 + tx;
    float* hout = g_h + ((size_t)b*64)*HW1*HW1 + y*HW1 + xc;
#pragma unroll 4
    for (int oc = 0; oc < 64; oc++) {
        float acc = bs[oc];
        const float* wo = &ws[oc*25];
#pragma unroll
        for (int k = 0; k < 25; k++) acc = fmaf(in[k], wo[k], acc);
        hout[(size_t)oc*HW1*HW1] = fmaxf(acc, 0.f);
    }
}

// ============================================================
// conv2: k9 s2 + bias + capsule squash -> g_u, packed f32x2.
// block: (b, 4 output rows) x 224 threads = 28 ow x 8 ocg.
// grid (7, 64) — weight staging amortized over 4 rows.
// ============================================================
__global__ __launch_bounds__(224) void conv2_kernel(
    const float* __restrict__ w, const float* __restrict__ bias)
{
    __shared__ float wsA[81*32];   // [q][ocg*4 + c], c=0..3
    __shared__ float wsB[81*32];   // c=4..7
    __shared__ float ins[15*64];   // input rows 8t..8t+14

    int b   = blockIdx.y;
    int t   = blockIdx.x;          // 0..6 -> output rows 4t..4t+3
    int tid = threadIdx.x;
    int ocg = tid & 7;
    int ow  = tid >> 3;
    int ow2 = ow * 2;

    u64 acc[4][4];
#pragma unroll
    for (int r = 0; r < 4; r++)
#pragma unroll
        for (int k = 0; k < 4; k++) acc[r][k] = 0ull;

    const float* hb = g_h + (size_t)b*64*HW1*HW1;

    for (int ic = 0; ic < 64; ic++) {
        __syncthreads();
        for (int i = tid; i < 64*81; i += 224) {
            int oc = i / 81, q = i - oc*81;
            float val = w[(size_t)(oc*64 + ic)*81 + q];
            int c7 = oc & 7, grp = oc >> 3;
            if (c7 < 4) wsA[q*32 + grp*4 + c7]       = val;
            else        wsB[q*32 + grp*4 + (c7 - 4)] = val;
        }
        const float* hrow = hb + (size_t)ic*HW1*HW1 + (8*t)*HW1;
        for (int i = tid; i < 15*64; i += 224) ins[i] = hrow[i];
        __syncthreads();

#pragma unroll
        for (int kh = 0; kh < 9; kh++) {
#pragma unroll
            for (int kw = 0; kw < 9; kw++) {
                int q = kh*9 + kw;
                const u64* WA = (const u64*)&wsA[q*32 + ocg*4];
                const u64* WB = (const u64*)&wsB[q*32 + ocg*4];
                u64 wa0 = WA[0], wa1 = WA[1];
                u64 wb0 = WB[0], wb1 = WB[1];
#pragma unroll
                for (int r = 0; r < 4; r++) {
                    u64 iv = pack2(ins[(kh + 2*r)*64 + ow2 + kw]);
                    ffma2(acc[r][0], iv, wa0); ffma2(acc[r][1], iv, wa1);
                    ffma2(acc[r][2], iv, wb0); ffma2(acc[r][3], iv, wb1);
                }
            }
        }
    }

    float bvals[8];
#pragma unroll
    for (int c = 0; c < 8; c++) bvals[c] = bias[ocg*8 + c];

#pragma unroll
    for (int r = 0; r < 4; r++) {
        float a[8];
#pragma unroll
        for (int k = 0; k < 4; k++) {
            float2 f = unpack2(acc[r][k]);
            a[2*k]   = f.x + bvals[2*k];
            a[2*k+1] = f.y + bvals[2*k+1];
        }
        float msq = 0.f;
#pragma unroll
        for (int c = 0; c < 8; c++) msq = fmaf(a[c], a[c], msq);
        float mag   = sqrtf(msq + EPS);
        float scale = msq / (1.f + msq) / (mag + EPS);
        int n = ocg*(HW2*HW2) + (4*t + r)*HW2 + ow;
        float* up = g_u + ((size_t)b*NROUTES + n)*JDIM;
        *(float4*)up       = make_float4(a[0]*scale, a[1]*scale, a[2]*scale, a[3]*scale);
        *(float4*)(up + 4) = make_float4(a[4]*scale, a[5]*scale, a[6]*scale, a[7]*scale);
    }
}

// ============================================================
// routing sweep. thread = (bb, o); 640 threads; 16 n per block.
// s accumulated in registers, flushed once via atomicAdd.
// iter0: c = 0.1. iter>0: logits = uh . g_v  (g_v = v0 or v0+v1)
// ============================================================
__global__ __launch_bounds__(640) void route_kernel(
    const float* __restrict__ W, int iter)
{
    __shared__ float Ws[2][NCAPS*WROW];
    __shared__ float ex[BATCH][NCAPS];

    int tid = threadIdx.x;
    int bb  = tid / 10;
    int o   = tid - bb*10;
    int n0  = blockIdx.x * NPER;

    float v[16];
    if (iter > 0) {
        const float4* vp = (const float4*)(g_v + (bb*NCAPS + o)*ODIM);
#pragma unroll
        for (int k = 0; k < 4; k++) {
            float4 f = vp[k];
            v[4*k] = f.x; v[4*k+1] = f.y; v[4*k+2] = f.z; v[4*k+3] = f.w;
        }
    }

    float acc[16];
#pragma unroll
    for (int i = 0; i < 16; i++) acc[i] = 0.f;

    float2 wpre = *(const float2*)(W + (size_t)n0*(NCAPS*ODIM*JDIM) + 2*tid);
    const float4* up0 = (const float4*)(g_u + ((size_t)bb*NROUTES + n0)*JDIM);
    float4 upa = up0[0], upb = up0[1];

    int buf = 0;
    for (int nn = 0; nn < NPER; nn++) {
        {
            int f  = 2*tid;
            int os = f >> 7;
            int r  = f & 127;
            *(float2*)&Ws[buf][os*WROW + r] = wpre;
        }
        __syncthreads();

        float4 ua = upa, ub = upb;
        if (nn < NPER-1) {
            const float* Wn = W + (size_t)(n0+nn+1)*(NCAPS*ODIM*JDIM);
            wpre = *(const float2*)(Wn + 2*tid);
            const float4* up = (const float4*)(g_u + ((size_t)bb*NROUTES + n0+nn+1)*JDIM);
            upa = up[0]; upb = up[1];
        }

        float uh[16];
        const float* wrow = &Ws[buf][o*WROW];
#pragma unroll
        for (int i = 0; i < 16; i++) {
            float4 wa = *(const float4*)(wrow + i*8);
            float4 wb = *(const float4*)(wrow + i*8 + 4);
            float s = wa.x * ua.x;
            s = fmaf(wa.y, ua.y, s); s = fmaf(wa.z, ua.z, s); s = fmaf(wa.w, ua.w, s);
            s = fmaf(wb.x, ub.x, s); s = fmaf(wb.y, ub.y, s);
            s = fmaf(wb.z, ub.z, s); s = fmaf(wb.w, ub.w, s);
            uh[i] = s;
        }

        float c;
        if (iter == 0) {
            c = 0.1f;
        } else {
            float bnew = 0.f;
#pragma unroll
            for (int i = 0; i < 16; i++) bnew = fmaf(uh[i], v[i], bnew);
            float e = __expf(bnew);
            ex[bb][o] = e;
            __syncthreads();
            float denom = 0.f;
#pragma unroll
            for (int k = 0; k < 10; k++) denom += ex[bb][k];
            c = __fdividef(e, denom);
        }
#pragma unroll
        for (int i = 0; i < 16; i++) acc[i] = fmaf(c, uh[i], acc[i]);

        buf ^= 1;
    }

    float* sp = g_s + (bb*NCAPS + o)*ODIM;
#pragma unroll
    for (int i = 0; i < 16; i++) atomicAdd(&sp[i], acc[i]);
}

// ============================================================
// squash s -> v / out; zero s for the next sweep.
// 2560 threads = (b,o) x 4 quads
// mode 0: g_v = v0 ; mode 1: g_v += v1 ; mode 2: write out
// ============================================================
__global__ __launch_bounds__(256) void squash_v_kernel(float* __restrict__ out, int mode)
{
    int tid  = blockIdx.x*256 + threadIdx.x;
    int boq  = tid >> 2;
    int quad = tid & 3;

    float4 s = *(const float4*)(g_s + boq*ODIM + quad*4);
    *(float4*)(g_s + boq*ODIM + quad*4) = make_float4(0.f,0.f,0.f,0.f);

    float part = s.x*s.x + s.y*s.y + s.z*s.z + s.w*s.w;
    part += __shfl_xor_sync(0xffffffff, part, 1);
    part += __shfl_xor_sync(0xffffffff, part, 2);
    float msq   = part;
    float mag   = sqrtf(msq + EPS);
    float scale = msq / (1.f + msq) / (mag + EPS);
    float4 vv = make_float4(s.x*scale, s.y*scale, s.z*scale, s.w*scale);

    if (mode == 0) {
        *(float4*)(g_v + boq*ODIM + quad*4) = vv;
    } else if (mode == 1) {
        float4 old = *(const float4*)(g_v + boq*ODIM + quad*4);
        old.x += vv.x; old.y += vv.y; old.z += vv.z; old.w += vv.w;
        *(float4*)(g_v + boq*ODIM + quad*4) = old;
    } else {
        *(float4*)(out + boq*ODIM + quad*4) = vv;
    }
}

// ============================================================
extern "C" void kernel_launch(void* const* d_in, const int* in_sizes, int n_in,
                              void* d_out, int out_size)
{
    const float* x   = (const float*)d_in[0];
    const float* c1w = (const float*)d_in[1];
    const float* c1b = (const float*)d_in[2];
    const float* pw  = (const float*)d_in[3];
    const float* pb  = (const float*)d_in[4];
    const float* W   = (const float*)d_in[5];
    float* out = (float*)d_out;

    zero_s_kernel<<<40, 256>>>();
    conv1_kernel<<<dim3(4,4,64), dim3(16,16)>>>(x, c1w, c1b);
    conv2_kernel<<<dim3(7,64), 224>>>(pw, pb);

    route_kernel<<<RBLOCKS, 640>>>(W, 0);
    squash_v_kernel<<<10, 256>>>(out, 0);
    route_kernel<<<RBLOCKS, 640>>>(W, 1);
    squash_v_kernel<<<10, 256>>>(out, 1);
    route_kernel<<<RBLOCKS, 640>>>(W, 2);
    squash_v_kernel<<<10, 256>>>(out, 2);
}

// round 5
// speedup vs baseline: 1.1970x; 1.1970x over previous
#include <cuda_runtime.h>
#include <math.h>

#define EPS 1e-9f

#define BATCH   64
#define HW1     64
#define HW2     28
#define NROUTES 6272
#define NCAPS   10
#define ODIM    16
#define JDIM    8

#define RBLOCKS 392
#define NPER    16
#define NREP    8        // s-accumulator replicas

typedef unsigned long long u64;

__device__ float g_h[(size_t)BATCH*64*HW1*HW1];      // conv1 out
__device__ float g_u[(size_t)NROUTES*BATCH*JDIM];    // primary caps, [n][b][8]
__device__ float g_v[BATCH*NCAPS*ODIM];              // v0, then v0+v1
__device__ float g_sR[NREP*BATCH*NCAPS*ODIM];        // replicated s accumulators

// ---------- packed fp32x2 helpers ----------
__device__ __forceinline__ u64 pack2(float x) {
    u64 r; asm("mov.b64 %0, {%1, %1};" : "=l"(r) : "f"(x)); return r;
}
__device__ __forceinline__ void ffma2(u64& d, u64 a, u64 b) {
    asm("fma.rn.f32x2 %0, %1, %2, %0;" : "+l"(d) : "l"(a), "l"(b));
}
__device__ __forceinline__ float2 unpack2(u64 a) {
    float2 f; asm("mov.b64 {%0, %1}, %2;" : "=f"(f.x), "=f"(f.y) : "l"(a)); return f;
}

// ============================================================
__global__ void zero_s_kernel() {
    int i = blockIdx.x * 256 + threadIdx.x;
    if (i < NREP*BATCH*NCAPS*ODIM) g_sR[i] = 0.f;
}

// ============================================================
// conv1: (64,1,64,64) -> (64,64,64,64), k5 pad2 + bias + relu
// ============================================================
__global__ __launch_bounds__(256) void conv1_kernel(
    const float* __restrict__ x, const float* __restrict__ w,
    const float* __restrict__ bias)
{
    __shared__ float xs[20][20];
    __shared__ float ws[64*25];
    __shared__ float bs[64];
    int b   = blockIdx.z;
    int ty0 = blockIdx.y * 16, tx0 = blockIdx.x * 16;
    int tid = threadIdx.y * 16 + threadIdx.x;

    for (int i = tid; i < 64*25; i += 256) ws[i] = w[i];
    if (tid < 64) bs[tid] = bias[tid];

    const float* xb = x + (size_t)b * HW1 * HW1;
    for (int i = tid; i < 400; i += 256) {
        int r = i / 20, c = i % 20;
        int gy = ty0 + r - 2, gx = tx0 + c - 2;
        float v = 0.f;
        if (gy >= 0 && gy < HW1 && gx >= 0 && gx < HW1) v = xb[gy*HW1 + gx];
        xs[r][c] = v;
    }
    __syncthreads();

    int ty = threadIdx.y, tx = threadIdx.x;
    float in[25];
#pragma unroll
    for (int kh = 0; kh < 5; kh++)
#pragma unroll
        for (int kw = 0; kw < 5; kw++)
            in[kh*5+kw] = xs[ty+kh][tx+kw];

    int y = ty0 + ty, xc = tx0 + tx;
    float* hout = g_h + ((size_t)b*64)*HW1*HW1 + y*HW1 + xc;
#pragma unroll 4
    for (int oc = 0; oc < 64; oc++) {
        float acc = bs[oc];
        const float* wo = &ws[oc*25];
#pragma unroll
        for (int k = 0; k < 25; k++) acc = fmaf(in[k], wo[k], acc);
        hout[(size_t)oc*HW1*HW1] = fmaxf(acc, 0.f);
    }
}

// ============================================================
// conv2: k9 s2 + bias + capsule squash -> g_u[n][b][8]
// 2-row micro-tile, packed f32x2, grid (14, 64) x 224 threads
// ============================================================
__global__ __launch_bounds__(224) void conv2_kernel(
    const float* __restrict__ w, const float* __restrict__ bias)
{
    __shared__ float wsA[81*32];   // [q][ocg*4 + c], c=0..3
    __shared__ float wsB[81*32];   // c=4..7
    __shared__ float ins[11*64];   // input rows 4t..4t+10

    int b   = blockIdx.y;
    int t   = blockIdx.x;          // 0..13
    int tid = threadIdx.x;
    int ocg = tid & 7;
    int ow  = tid >> 3;
    int ow2 = ow * 2;

    u64 a0[4], a1[4];
#pragma unroll
    for (int k = 0; k < 4; k++) { a0[k] = 0ull; a1[k] = 0ull; }

    const float* hb = g_h + (size_t)b*64*HW1*HW1;

    for (int ic = 0; ic < 64; ic++) {
        __syncthreads();
        for (int i = tid; i < 64*81; i += 224) {
            int oc = i / 81, q = i - oc*81;
            float val = w[(size_t)(oc*64 + ic)*81 + q];
            int c7 = oc & 7, grp = oc >> 3;
            if (c7 < 4) wsA[q*32 + grp*4 + c7]       = val;
            else        wsB[q*32 + grp*4 + (c7 - 4)] = val;
        }
        const float* hrow = hb + (size_t)ic*HW1*HW1 + (4*t)*HW1;
        for (int i = tid; i < 11*64; i += 224) ins[i] = hrow[i];
        __syncthreads();

#pragma unroll
        for (int kh = 0; kh < 9; kh++) {
#pragma unroll
            for (int kw = 0; kw < 9; kw++) {
                int q = kh*9 + kw;
                const u64* WA = (const u64*)&wsA[q*32 + ocg*4];
                const u64* WB = (const u64*)&wsB[q*32 + ocg*4];
                u64 wa0 = WA[0], wa1 = WA[1];
                u64 wb0 = WB[0], wb1 = WB[1];
                u64 i0 = pack2(ins[kh*64 + ow2 + kw]);
                u64 i1 = pack2(ins[(kh+2)*64 + ow2 + kw]);
                ffma2(a0[0], i0, wa0); ffma2(a0[1], i0, wa1);
                ffma2(a0[2], i0, wb0); ffma2(a0[3], i0, wb1);
                ffma2(a1[0], i1, wa0); ffma2(a1[1], i1, wa1);
                ffma2(a1[2], i1, wb0); ffma2(a1[3], i1, wb1);
            }
        }
    }

    float bvals[8];
#pragma unroll
    for (int c = 0; c < 8; c++) bvals[c] = bias[ocg*8 + c];

    int oh0 = 2*t;
#pragma unroll
    for (int r = 0; r < 2; r++) {
        u64* ap = r ? a1 : a0;
        float a[8];
#pragma unroll
        for (int k = 0; k < 4; k++) {
            float2 f = unpack2(ap[k]);
            a[2*k]   = f.x + bvals[2*k];
            a[2*k+1] = f.y + bvals[2*k+1];
        }
        float msq = 0.f;
#pragma unroll
        for (int c = 0; c < 8; c++) msq = fmaf(a[c], a[c], msq);
        float mag   = sqrtf(msq + EPS);
        float scale = msq / (1.f + msq) / (mag + EPS);
        int n = ocg*(HW2*HW2) + (oh0+r)*HW2 + ow;
        float* up = g_u + ((size_t)n*BATCH + b)*JDIM;   // transposed [n][b][8]
        *(float4*)up       = make_float4(a[0]*scale, a[1]*scale, a[2]*scale, a[3]*scale);
        *(float4*)(up + 4) = make_float4(a[4]*scale, a[5]*scale, a[6]*scale, a[7]*scale);
    }
}

// ============================================================
// routing sweep, broadcast layout:
//   warp w = (bbgroup, o):  o = w % 10, bb = (w/10)*32 + lane
// -> all Ws reads are warp-uniform (1-phase broadcast LDS),
//    all g_u reads are lane-coalesced ([n][b][8] layout).
// s accumulated in regs; flushed to 1 of 8 replicas by atomics.
// iter0: c = 0.1. iter>0: logits = uh . g_v (v0, then v0+v1)
// ============================================================
__global__ __launch_bounds__(640) void route_kernel(
    const float* __restrict__ W, int iter)
{
    __shared__ float Ws[2][NCAPS*ODIM*JDIM];   // 2 x 1280
    __shared__ float ex[NCAPS*BATCH];          // [o][bb]

    int tid  = threadIdx.x;
    int wrp  = tid >> 5;
    int lane = tid & 31;
    int o    = wrp % 10;
    int bb   = (wrp / 10) * 32 + lane;
    int n0   = blockIdx.x * NPER;

    float v[16];
    if (iter > 0) {
        const float4* vp = (const float4*)(g_v + (bb*NCAPS + o)*ODIM);
#pragma unroll
        for (int k = 0; k < 4; k++) {
            float4 f = vp[k];
            v[4*k] = f.x; v[4*k+1] = f.y; v[4*k+2] = f.z; v[4*k+3] = f.w;
        }
    }

    float acc[16];
#pragma unroll
    for (int i = 0; i < 16; i++) acc[i] = 0.f;

    // prefetch n0
    float2 wpre = *(const float2*)(W + (size_t)n0*(NCAPS*ODIM*JDIM) + 2*tid);
    const float4* up0 = (const float4*)(g_u + ((size_t)n0*BATCH + bb)*JDIM);
    float4 upa = up0[0], upb = up0[1];

    int buf = 0;
    for (int nn = 0; nn < NPER; nn++) {
        *(float2*)&Ws[buf][2*tid] = wpre;
        __syncthreads();

        float4 ua = upa, ub = upb;
        if (nn < NPER-1) {
            int n1 = n0 + nn + 1;
            wpre = *(const float2*)(W + (size_t)n1*(NCAPS*ODIM*JDIM) + 2*tid);
            const float4* up = (const float4*)(g_u + ((size_t)n1*BATCH + bb)*JDIM);
            upa = up[0]; upb = up[1];
        }

        float uh[16];
        const float* wrow = &Ws[buf][o*(ODIM*JDIM)];   // warp-uniform
#pragma unroll
        for (int i = 0; i < 16; i++) {
            float4 wa = *(const float4*)(wrow + i*8);
            float4 wb = *(const float4*)(wrow + i*8 + 4);
            float s = wa.x * ua.x;
            s = fmaf(wa.y, ua.y, s); s = fmaf(wa.z, ua.z, s); s = fmaf(wa.w, ua.w, s);
            s = fmaf(wb.x, ub.x, s); s = fmaf(wb.y, ub.y, s);
            s = fmaf(wb.z, ub.z, s); s = fmaf(wb.w, ub.w, s);
            uh[i] = s;
        }

        float c;
        if (iter == 0) {
            c = 0.1f;
        } else {
            float bnew = 0.f;
#pragma unroll
            for (int i = 0; i < 16; i++) bnew = fmaf(uh[i], v[i], bnew);
            float e = __expf(bnew);
            ex[o*BATCH + bb] = e;
            __syncthreads();
            float denom = 0.f;
#pragma unroll
            for (int k = 0; k < 10; k++) denom += ex[k*BATCH + bb];
            c = __fdividef(e, denom);
        }
#pragma unroll
        for (int i = 0; i < 16; i++) acc[i] = fmaf(c, uh[i], acc[i]);

        buf ^= 1;
    }

    int rep = blockIdx.x & (NREP-1);
    float* sp = g_sR + rep*(BATCH*NCAPS*ODIM) + (bb*NCAPS + o)*ODIM;
#pragma unroll
    for (int i = 0; i < 16; i++) atomicAdd(&sp[i], acc[i]);
}

// ============================================================
// sum 8 replicas, squash -> v / out; re-zero replicas.
// 2560 threads = (b,o) x 4 quads
// mode 0: g_v = v0 ; mode 1: g_v += v1 ; mode 2: write out
// ============================================================
__global__ __launch_bounds__(256) void squash_v_kernel(float* __restrict__ out, int mode)
{
    int tid  = blockIdx.x*256 + threadIdx.x;
    int boq  = tid >> 2;
    int quad = tid & 3;

    float4 s = make_float4(0.f, 0.f, 0.f, 0.f);
#pragma unroll
    for (int r = 0; r < NREP; r++) {
        float* p = g_sR + r*(BATCH*NCAPS*ODIM) + boq*ODIM + quad*4;
        float4 t = *(const float4*)p;
        *(float4*)p = make_float4(0.f, 0.f, 0.f, 0.f);
        s.x += t.x; s.y += t.y; s.z += t.z; s.w += t.w;
    }

    float part = s.x*s.x + s.y*s.y + s.z*s.z + s.w*s.w;
    part += __shfl_xor_sync(0xffffffff, part, 1);
    part += __shfl_xor_sync(0xffffffff, part, 2);
    float msq   = part;
    float mag   = sqrtf(msq + EPS);
    float scale = msq / (1.f + msq) / (mag + EPS);
    float4 vv = make_float4(s.x*scale, s.y*scale, s.z*scale, s.w*scale);

    if (mode == 0) {
        *(float4*)(g_v + boq*ODIM + quad*4) = vv;
    } else if (mode == 1) {
        float4 old = *(const float4*)(g_v + boq*ODIM + quad*4);
        old.x += vv.x; old.y += vv.y; old.z += vv.z; old.w += vv.w;
        *(float4*)(g_v + boq*ODIM + quad*4) = old;
    } else {
        *(float4*)(out + boq*ODIM + quad*4) = vv;
    }
}

// ============================================================
extern "C" void kernel_launch(void* const* d_in, const int* in_sizes, int n_in,
                              void* d_out, int out_size)
{
    const float* x   = (const float*)d_in[0];
    const float* c1w = (const float*)d_in[1];
    const float* c1b = (const float*)d_in[2];
    const float* pw  = (const float*)d_in[3];
    const float* pb  = (const float*)d_in[4];
    const float* W   = (const float*)d_in[5];
    float* out = (float*)d_out;

    zero_s_kernel<<<(NREP*BATCH*NCAPS*ODIM + 255)/256, 256>>>();
    conv1_kernel<<<dim3(4,4,64), dim3(16,16)>>>(x, c1w, c1b);
    conv2_kernel<<<dim3(14,64), 224>>>(pw, pb);

    route_kernel<<<RBLOCKS, 640>>>(W, 0);
    squash_v_kernel<<<10, 256>>>(out, 0);
    route_kernel<<<RBLOCKS, 640>>>(W, 1);
    squash_v_kernel<<<10, 256>>>(out, 1);
    route_kernel<<<RBLOCKS, 640>>>(W, 2);
    squash_v_kernel<<<10, 256>>>(out, 2);
}

// round 7
// speedup vs baseline: 2.0296x; 1.6956x over previous
#include <cuda_runtime.h>
#include <cstdint>
#include <math.h>

#define EPS 1e-9f

#define BATCH   64
#define HW1     64
#define HW2     28
#define NROUTES 6272
#define NCAPS   10
#define ODIM    16
#define JDIM    8

#define RBLOCKS 392
#define NPER    16
#define NREP    8        // s-accumulator replicas

typedef unsigned long long u64;
typedef unsigned int       u32;

__device__ float g_h[(size_t)BATCH*64*HW1*HW1];      // conv1 out [b][ic][ih][iw]
__device__ float g_wT[64*81*64];                     // conv2 weights [ic][q][slot]
__device__ float g_u[(size_t)NROUTES*BATCH*JDIM];    // primary caps [n][b][8]
__device__ float g_v[BATCH*NCAPS*ODIM];              // v0, then v0+v1
__device__ float g_sR[NREP*BATCH*NCAPS*ODIM];        // replicated s accumulators

// ---------- packed fp32x2 helpers ----------
__device__ __forceinline__ u64 pack2(float x) {
    u64 r; asm("mov.b64 %0, {%1, %1};" : "=l"(r) : "f"(x)); return r;
}
__device__ __forceinline__ void ffma2(u64& d, u64 a, u64 b) {
    asm("fma.rn.f32x2 %0, %1, %2, %0;" : "+l"(d) : "l"(a), "l"(b));
}
__device__ __forceinline__ float2 unpack2(u64 a) {
    float2 f; asm("mov.b64 {%0, %1}, %2;" : "=f"(f.x), "=f"(f.y) : "l"(a)); return f;
}
// ---------- cp.async helpers ----------
__device__ __forceinline__ void cpasync16(u32 saddr, const void* gaddr) {
    asm volatile("cp.async.cg.shared.global [%0], [%1], 16;" :: "r"(saddr), "l"(gaddr));
}
__device__ __forceinline__ void cpcommit() {
    asm volatile("cp.async.commit_group;");
}
__device__ __forceinline__ void cpwait0() {
    asm volatile("cp.async.wait_group 0;");
}

// ============================================================
// one-time weight transpose for conv2:
// g_wT[ic][q][slot], slot = grp*4 + (c7&3) + (c7>=4 ? 32 : 0)
// (oc = grp*8 + c7) -> staging becomes a linear float4 copy
// ============================================================
__global__ __launch_bounds__(256) void w_transform_kernel(const float* __restrict__ w)
{
    int idx = blockIdx.x*256 + threadIdx.x;            // = oc*5184 + ic*81 + q
    if (idx >= 64*64*81) return;
    int oc  = idx / 5184;
    int rem = idx - oc*5184;
    int ic  = rem / 81;
    int q   = rem - ic*81;
    int c7  = oc & 7, grp = oc >> 3;
    int slot = grp*4 + (c7 & 3) + ((c7 >= 4) ? 32 : 0);
    g_wT[(size_t)ic*5184 + q*64 + slot] = w[idx];
}

// ============================================================
// conv1: (64,1,64,64) -> (64,64,64,64), k5 pad2 + bias + relu
// ============================================================
__global__ __launch_bounds__(256) void conv1_kernel(
    const float* __restrict__ x, const float* __restrict__ w,
    const float* __restrict__ bias)
{
    __shared__ float xs[20][20];
    __shared__ float ws[64*25];
    __shared__ float bs[64];
    int b   = blockIdx.z;
    int ty0 = blockIdx.y * 16, tx0 = blockIdx.x * 16;
    int tid = threadIdx.y * 16 + threadIdx.x;

    for (int i = tid; i < 64*25; i += 256) ws[i] = w[i];
    if (tid < 64) bs[tid] = bias[tid];

    const float* xb = x + (size_t)b * HW1 * HW1;
    for (int i = tid; i < 400; i += 256) {
        int r = i / 20, c = i % 20;
        int gy = ty0 + r - 2, gx = tx0 + c - 2;
        float v = 0.f;
        if (gy >= 0 && gy < HW1 && gx >= 0 && gx < HW1) v = xb[gy*HW1 + gx];
        xs[r][c] = v;
    }
    __syncthreads();

    int ty = threadIdx.y, tx = threadIdx.x;
    float in[25];
#pragma unroll
    for (int kh = 0; kh < 5; kh++)
#pragma unroll
        for (int kw = 0; kw < 5; kw++)
            in[kh*5+kw] = xs[ty+kh][tx+kw];

    int y = ty0 + ty, xc = tx0 + tx;
    float* hout = g_h + ((size_t)b*64)*HW1*HW1 + y*HW1 + xc;
#pragma unroll 4
    for (int oc = 0; oc < 64; oc++) {
        float acc = bs[oc];
        const float* wo = &ws[oc*25];
#pragma unroll
        for (int k = 0; k < 25; k++) acc = fmaf(in[k], wo[k], acc);
        hout[(size_t)oc*HW1*HW1] = fmaxf(acc, 0.f);
    }
}

// ============================================================
// conv2: k9 s2 + bias + capsule squash -> g_u[n][b][8]
// cp.async double-buffered staging (1 sync per ic, latency hidden)
// 2-row micro-tile, packed f32x2, grid (14, 64) x 224 threads
// ============================================================
__global__ __launch_bounds__(224) void conv2_kernel(const float* __restrict__ bias)
{
    __shared__ float wsd[2][81*64];    // [q][slot] per buffer
    __shared__ float ins[2][11*64];    // input rows 4t..4t+10

    int b   = blockIdx.y;
    int t   = blockIdx.x;              // 0..13
    int tid = threadIdx.x;
    int ocg = tid & 7;
    int ow  = tid >> 3;
    int ow2 = ow * 2;

    u32 s_wsd0 = (u32)__cvta_generic_to_shared(&wsd[0][0]);
    u32 s_wsd1 = (u32)__cvta_generic_to_shared(&wsd[1][0]);
    u32 s_ins0 = (u32)__cvta_generic_to_shared(&ins[0][0]);
    u32 s_ins1 = (u32)__cvta_generic_to_shared(&ins[1][0]);

    const float* hb = g_h + (size_t)b*64*HW1*HW1 + (size_t)(4*t)*HW1;

    // stage(ic, buf): weights 1296 float4 + inputs 176 float4
    auto stage = [&](int ic, int buf) {
        u32 sw = buf ? s_wsd1 : s_wsd0;
        u32 si = buf ? s_ins1 : s_ins0;
        const float* wsrc = g_wT + (size_t)ic*5184;
        const float* isrc = hb + (size_t)ic*HW1*HW1;
#pragma unroll
        for (int k = 0; k < 6; k++) {
            int i = tid + k*224;
            if (i < 1296) cpasync16(sw + i*16, wsrc + i*4);
        }
        if (tid < 176) cpasync16(si + tid*16, isrc + tid*4);
    };

    u64 a0[4], a1[4];
#pragma unroll
    for (int k = 0; k < 4; k++) { a0[k] = 0ull; a1[k] = 0ull; }

    stage(0, 0); cpcommit();

    for (int ic = 0; ic < 64; ic++) {
        int buf = ic & 1;
        cpwait0();
        __syncthreads();               // staged data visible; prev compute done
        if (ic + 1 < 64) { stage(ic+1, buf ^ 1); cpcommit(); }

        const float* wb_ = wsd[buf];
        const float* ib_ = ins[buf];
#pragma unroll
        for (int kh = 0; kh < 9; kh++) {
#pragma unroll
            for (int kw = 0; kw < 9; kw++) {
                int q = kh*9 + kw;
                const u64* WA = (const u64*)&wb_[q*64 + ocg*4];
                const u64* WB = (const u64*)&wb_[q*64 + 32 + ocg*4];
                u64 wa0 = WA[0], wa1 = WA[1];
                u64 wb0 = WB[0], wb1 = WB[1];
                u64 i0 = pack2(ib_[kh*64 + ow2 + kw]);
                u64 i1 = pack2(ib_[(kh+2)*64 + ow2 + kw]);
                ffma2(a0[0], i0, wa0); ffma2(a0[1], i0, wa1);
                ffma2(a0[2], i0, wb0); ffma2(a0[3], i0, wb1);
                ffma2(a1[0], i1, wa0); ffma2(a1[1], i1, wa1);
                ffma2(a1[2], i1, wb0); ffma2(a1[3], i1, wb1);
            }
        }
    }

    float bvals[8];
#pragma unroll
    for (int c = 0; c < 8; c++) bvals[c] = bias[ocg*8 + c];

    int oh0 = 2*t;
#pragma unroll
    for (int r = 0; r < 2; r++) {
        u64* ap = r ? a1 : a0;
        float a[8];
#pragma unroll
        for (int k = 0; k < 4; k++) {
            float2 f = unpack2(ap[k]);
            a[2*k]   = f.x + bvals[2*k];
            a[2*k+1] = f.y + bvals[2*k+1];
        }
        float msq = 0.f;
#pragma unroll
        for (int c = 0; c < 8; c++) msq = fmaf(a[c], a[c], msq);
        float mag   = sqrtf(msq + EPS);
        float scale = msq / (1.f + msq) / (mag + EPS);
        int n = ocg*(HW2*HW2) + (oh0+r)*HW2 + ow;
        float* up = g_u + ((size_t)n*BATCH + b)*JDIM;   // [n][b][8]
        *(float4*)up       = make_float4(a[0]*scale, a[1]*scale, a[2]*scale, a[3]*scale);
        *(float4*)(up + 4) = make_float4(a[4]*scale, a[5]*scale, a[6]*scale, a[7]*scale);
    }
}

// ============================================================
// routing sweep, broadcast layout:
//   warp w = (bbgroup, o):  o = w % 10, bb = (w/10)*32 + lane
// -> Ws reads warp-uniform (broadcast), g_u reads coalesced.
// s in registers, flushed to 1 of 8 replicas via atomics.
// iter0: c = 0.1. iter>0: logits = uh . g_v (v0, then v0+v1)
// ============================================================
__global__ __launch_bounds__(640) void route_kernel(
    const float* __restrict__ W, int iter)
{
    __shared__ float Ws[2][NCAPS*ODIM*JDIM];   // 2 x 1280
    __shared__ float ex[NCAPS*BATCH];          // [o][bb]

    int tid  = threadIdx.x;
    int wrp  = tid >> 5;
    int lane = tid & 31;
    int o    = wrp % 10;
    int bb   = (wrp / 10) * 32 + lane;
    int n0   = blockIdx.x * NPER;

    float v[16];
    if (iter > 0) {
        const float4* vp = (const float4*)(g_v + (bb*NCAPS + o)*ODIM);
#pragma unroll
        for (int k = 0; k < 4; k++) {
            float4 f = vp[k];
            v[4*k] = f.x; v[4*k+1] = f.y; v[4*k+2] = f.z; v[4*k+3] = f.w;
        }
    }

    float acc[16];
#pragma unroll
    for (int i = 0; i < 16; i++) acc[i] = 0.f;

    float2 wpre = *(const float2*)(W + (size_t)n0*(NCAPS*ODIM*JDIM) + 2*tid);
    const float4* up0 = (const float4*)(g_u + ((size_t)n0*BATCH + bb)*JDIM);
    float4 upa = up0[0], upb = up0[1];

    int buf = 0;
    for (int nn = 0; nn < NPER; nn++) {
        *(float2*)&Ws[buf][2*tid] = wpre;
        __syncthreads();

        float4 ua = upa, ub = upb;
        if (nn < NPER-1) {
            int n1 = n0 + nn + 1;
            wpre = *(const float2*)(W + (size_t)n1*(NCAPS*ODIM*JDIM) + 2*tid);
            const float4* up = (const float4*)(g_u + ((size_t)n1*BATCH + bb)*JDIM);
            upa = up[0]; upb = up[1];
        }

        float uh[16];
        const float* wrow = &Ws[buf][o*(ODIM*JDIM)];   // warp-uniform
#pragma unroll
        for (int i = 0; i < 16; i++) {
            float4 wa = *(const float4*)(wrow + i*8);
            float4 wb = *(const float4*)(wrow + i*8 + 4);
            float s = wa.x * ua.x;
            s = fmaf(wa.y, ua.y, s); s = fmaf(wa.z, ua.z, s); s = fmaf(wa.w, ua.w, s);
            s = fmaf(wb.x, ub.x, s); s = fmaf(wb.y, ub.y, s);
            s = fmaf(wb.z, ub.z, s); s = fmaf(wb.w, ub.w, s);
            uh[i] = s;
        }

        float c;
        if (iter == 0) {
            c = 0.1f;
        } else {
            float bnew = 0.f;
#pragma unroll
            for (int i = 0; i < 16; i++) bnew = fmaf(uh[i], v[i], bnew);
            float e = __expf(bnew);
            ex[o*BATCH + bb] = e;
            __syncthreads();
            float denom = 0.f;
#pragma unroll
            for (int k = 0; k < 10; k++) denom += ex[k*BATCH + bb];
            c = __fdividef(e, denom);
        }
#pragma unroll
        for (int i = 0; i < 16; i++) acc[i] = fmaf(c, uh[i], acc[i]);

        buf ^= 1;
    }

    int rep = blockIdx.x & (NREP-1);
    float* sp = g_sR + rep*(BATCH*NCAPS*ODIM) + (bb*NCAPS + o)*ODIM;
#pragma unroll
    for (int i = 0; i < 16; i++) atomicAdd(&sp[i], acc[i]);
}

// ============================================================
// sum 8 replicas, squash -> v / out; re-zero replicas.
// 2560 threads = (b,o) x 4 quads
// mode 0: g_v = v0 ; mode 1: g_v += v1 ; mode 2: write out
// ============================================================
__global__ __launch_bounds__(256) void squash_v_kernel(float* __restrict__ out, int mode)
{
    int tid  = blockIdx.x*256 + threadIdx.x;
    int boq  = tid >> 2;
    int quad = tid & 3;

    float4 s = make_float4(0.f, 0.f, 0.f, 0.f);
#pragma unroll
    for (int r = 0; r < NREP; r++) {
        float* p = g_sR + r*(BATCH*NCAPS*ODIM) + boq*ODIM + quad*4;
        float4 t = *(const float4*)p;
        *(float4*)p = make_float4(0.f, 0.f, 0.f, 0.f);
        s.x += t.x; s.y += t.y; s.z += t.z; s.w += t.w;
    }

    float part = s.x*s.x + s.y*s.y + s.z*s.z + s.w*s.w;
    part += __shfl_xor_sync(0xffffffff, part, 1);
    part += __shfl_xor_sync(0xffffffff, part, 2);
    float msq   = part;
    float mag   = sqrtf(msq + EPS);
    float scale = msq / (1.f + msq) / (mag + EPS);
    float4 vv = make_float4(s.x*scale, s.y*scale, s.z*scale, s.w*scale);

    if (mode == 0) {
        *(float4*)(g_v + boq*ODIM + quad*4) = vv;
    } else if (mode == 1) {
        float4 old = *(const float4*)(g_v + boq*ODIM + quad*4);
        old.x += vv.x; old.y += vv.y; old.z += vv.z; old.w += vv.w;
        *(float4*)(g_v + boq*ODIM + quad*4) = old;
    } else {
        *(float4*)(out + boq*ODIM + quad*4) = vv;
    }
}

// ============================================================
extern "C" void kernel_launch(void* const* d_in, const int* in_sizes, int n_in,
                              void* d_out, int out_size)
{
    const float* x   = (const float*)d_in[0];
    const float* c1w = (const float*)d_in[1];
    const float* c1b = (const float*)d_in[2];
    const float* pw  = (const float*)d_in[3];
    const float* pb  = (const float*)d_in[4];
    const float* W   = (const float*)d_in[5];
    float* out = (float*)d_out;

    w_transform_kernel<<<(64*64*81 + 255)/256, 256>>>(pw);
    conv1_kernel<<<dim3(4,4,64), dim3(16,16)>>>(x, c1w, c1b);
    conv2_kernel<<<dim3(14,64), 224>>>(pb);

    route_kernel<<<RBLOCKS, 640>>>(W, 0);
    squash_v_kernel<<<10, 256>>>(out, 0);
    route_kernel<<<RBLOCKS, 640>>>(W, 1);
    squash_v_kernel<<<10, 256>>>(out, 1);
    route_kernel<<<RBLOCKS, 640>>>(W, 2);
    squash_v_kernel<<<10, 256>>>(out, 2);
}

// round 8
// speedup vs baseline: 2.9876x; 1.4720x over previous
#include <cuda_runtime.h>
#include <cstdint>
#include <math.h>

#define EPS 1e-9f

#define BATCH   64
#define HW1     64
#define HW2     28
#define NROUTES 6272
#define NCAPS   10
#define ODIM    16
#define JDIM    8

#define NPER    16       // n's per route block
#define NREP    8        // s-accumulator replicas

typedef unsigned long long u64;
typedef unsigned int       u32;

__device__ float g_h[(size_t)BATCH*64*HW1*HW1];      // conv1 out [b][ic][ih][iw]
__device__ float g_wT[64*81*64];                     // conv2 weights [ic][q][slot]
__device__ float g_u[(size_t)NROUTES*BATCH*JDIM];    // primary caps [n][b][8]
__device__ float g_v[BATCH*NCAPS*ODIM];              // v0, then v0+v1
__device__ float g_sR[NREP*BATCH*NCAPS*ODIM];        // replicated s accumulators

// ---------- packed fp32x2 helpers ----------
__device__ __forceinline__ u64 pack2(float x) {
    u64 r; asm("mov.b64 %0, {%1, %1};" : "=l"(r) : "f"(x)); return r;
}
__device__ __forceinline__ void ffma2(u64& d, u64 a, u64 b) {
    asm("fma.rn.f32x2 %0, %1, %2, %0;" : "+l"(d) : "l"(a), "l"(b));
}
__device__ __forceinline__ float2 unpack2(u64 a) {
    float2 f; asm("mov.b64 {%0, %1}, %2;" : "=f"(f.x), "=f"(f.y) : "l"(a)); return f;
}
// ---------- cp.async helpers ----------
__device__ __forceinline__ void cpasync16(u32 saddr, const void* gaddr) {
    asm volatile("cp.async.cg.shared.global [%0], [%1], 16;" :: "r"(saddr), "l"(gaddr));
}
__device__ __forceinline__ void cpcommit() {
    asm volatile("cp.async.commit_group;");
}
__device__ __forceinline__ void cpwait0() {
    asm volatile("cp.async.wait_group 0;");
}

// ============================================================
// one-time weight transpose for conv2:
// g_wT[ic][q][slot], slot = grp*4 + (c7&3) + (c7>=4 ? 32 : 0)
// ============================================================
__global__ __launch_bounds__(256) void w_transform_kernel(const float* __restrict__ w)
{
    int idx = blockIdx.x*256 + threadIdx.x;            // = oc*5184 + ic*81 + q
    if (idx >= 64*64*81) return;
    int oc  = idx / 5184;
    int rem = idx - oc*5184;
    int ic  = rem / 81;
    int q   = rem - ic*81;
    int c7  = oc & 7, grp = oc >> 3;
    int slot = grp*4 + (c7 & 3) + ((c7 >= 4) ? 32 : 0);
    g_wT[(size_t)ic*5184 + q*64 + slot] = w[idx];
}

// ============================================================
// conv1: (64,1,64,64) -> (64,64,64,64), k5 pad2 + bias + relu
// ============================================================
__global__ __launch_bounds__(256) void conv1_kernel(
    const float* __restrict__ x, const float* __restrict__ w,
    const float* __restrict__ bias)
{
    __shared__ float xs[20][20];
    __shared__ float ws[64*25];
    __shared__ float bs[64];
    int b   = blockIdx.z;
    int ty0 = blockIdx.y * 16, tx0 = blockIdx.x * 16;
    int tid = threadIdx.y * 16 + threadIdx.x;

    for (int i = tid; i < 64*25; i += 256) ws[i] = w[i];
    if (tid < 64) bs[tid] = bias[tid];

    const float* xb = x + (size_t)b * HW1 * HW1;
    for (int i = tid; i < 400; i += 256) {
        int r = i / 20, c = i % 20;
        int gy = ty0 + r - 2, gx = tx0 + c - 2;
        float v = 0.f;
        if (gy >= 0 && gy < HW1 && gx >= 0 && gx < HW1) v = xb[gy*HW1 + gx];
        xs[r][c] = v;
    }
    __syncthreads();

    int ty = threadIdx.y, tx = threadIdx.x;
    float in[25];
#pragma unroll
    for (int kh = 0; kh < 5; kh++)
#pragma unroll
        for (int kw = 0; kw < 5; kw++)
            in[kh*5+kw] = xs[ty+kh][tx+kw];

    int y = ty0 + ty, xc = tx0 + tx;
    float* hout = g_h + ((size_t)b*64)*HW1*HW1 + y*HW1 + xc;
#pragma unroll 4
    for (int oc = 0; oc < 64; oc++) {
        float acc = bs[oc];
        const float* wo = &ws[oc*25];
#pragma unroll
        for (int k = 0; k < 25; k++) acc = fmaf(in[k], wo[k], acc);
        hout[(size_t)oc*HW1*HW1] = fmaxf(acc, 0.f);
    }
}

// ============================================================
// conv2: k9 s2 + bias + capsule squash -> g_u[n][b][8]
// cp.async double-buffered staging; 4-row micro-tile (W LDS
// amortized over 4 rows). grid (7, 64) x 224 threads.
// dynamic smem: wsd[2][5184] + ins[2][960] = 49.2KB
// ============================================================
#define C2_WSZ 5184          // 81*64
#define C2_ISZ 960           // 15*64
#define C2_SMEM ((2*C2_WSZ + 2*C2_ISZ)*4)

__global__ __launch_bounds__(224) void conv2_kernel(const float* __restrict__ bias)
{
    extern __shared__ float dsm[];
    float* wsd = dsm;                 // [2][5184]
    float* ins = dsm + 2*C2_WSZ;      // [2][960]

    int b   = blockIdx.y;
    int t   = blockIdx.x;              // 0..6 -> output rows 4t..4t+3
    int tid = threadIdx.x;
    int ocg = tid & 7;
    int ow  = tid >> 3;
    int ow2 = ow * 2;

    u32 s_wsd = (u32)__cvta_generic_to_shared(wsd);
    u32 s_ins = (u32)__cvta_generic_to_shared(ins);

    const float* hb = g_h + (size_t)b*64*HW1*HW1 + (size_t)(8*t)*HW1;

    auto stage = [&](int ic, int buf) {
        u32 sw = s_wsd + buf*(C2_WSZ*4);
        u32 si = s_ins + buf*(C2_ISZ*4);
        const float* wsrc = g_wT + (size_t)ic*C2_WSZ;
        const float* isrc = hb + (size_t)ic*HW1*HW1;
#pragma unroll
        for (int k = 0; k < 6; k++) {
            int i = tid + k*224;
            if (i < 1296) cpasync16(sw + i*16, wsrc + i*4);
        }
#pragma unroll
        for (int k = 0; k < 2; k++) {
            int i = tid + k*224;
            if (i < 240) cpasync16(si + i*16, isrc + i*4);
        }
    };

    u64 acc[4][4];
#pragma unroll
    for (int r = 0; r < 4; r++)
#pragma unroll
        for (int k = 0; k < 4; k++) acc[r][k] = 0ull;

    stage(0, 0); cpcommit();

    for (int ic = 0; ic < 64; ic++) {
        int buf = ic & 1;
        cpwait0();
        __syncthreads();
        if (ic + 1 < 64) { stage(ic+1, buf ^ 1); cpcommit(); }

        const float* wb_ = wsd + buf*C2_WSZ;
        const float* ib_ = ins + buf*C2_ISZ;
#pragma unroll
        for (int kh = 0; kh < 9; kh++) {
#pragma unroll
            for (int kw = 0; kw < 9; kw++) {
                int q = kh*9 + kw;
                const u64* WA = (const u64*)&wb_[q*64 + ocg*4];
                const u64* WB = (const u64*)&wb_[q*64 + 32 + ocg*4];
                u64 wa0 = WA[0], wa1 = WA[1];
                u64 wb0 = WB[0], wb1 = WB[1];
#pragma unroll
                for (int r = 0; r < 4; r++) {
                    u64 iv = pack2(ib_[(kh + 2*r)*64 + ow2 + kw]);
                    ffma2(acc[r][0], iv, wa0); ffma2(acc[r][1], iv, wa1);
                    ffma2(acc[r][2], iv, wb0); ffma2(acc[r][3], iv, wb1);
                }
            }
        }
    }

    float bvals[8];
#pragma unroll
    for (int c = 0; c < 8; c++) bvals[c] = bias[ocg*8 + c];

#pragma unroll
    for (int r = 0; r < 4; r++) {
        float a[8];
#pragma unroll
        for (int k = 0; k < 4; k++) {
            float2 f = unpack2(acc[r][k]);
            a[2*k]   = f.x + bvals[2*k];
            a[2*k+1] = f.y + bvals[2*k+1];
        }
        float msq = 0.f;
#pragma unroll
        for (int c = 0; c < 8; c++) msq = fmaf(a[c], a[c], msq);
        float mag   = sqrtf(msq + EPS);
        float scale = msq / (1.f + msq) / (mag + EPS);
        int n = ocg*(HW2*HW2) + (4*t + r)*HW2 + ow;
        float* up = g_u + ((size_t)n*BATCH + b)*JDIM;   // [n][b][8]
        *(float4*)up       = make_float4(a[0]*scale, a[1]*scale, a[2]*scale, a[3]*scale);
        *(float4*)(up + 4) = make_float4(a[4]*scale, a[5]*scale, a[6]*scale, a[7]*scale);
    }
}

// ============================================================
// routing sweep: 320-thread blocks (warp = o, lane = bb-half),
// grid (392, 2). ALL 16 n's W + u staged once via cp.async ->
// iter0 loop is sync-free; iter>=1 has ONE sync per n with a
// parity-double-buffered ex array.
// dynamic smem: Ws 16*1280 + us 16*256 + ex 2*10*32 = 101KB
// ============================================================
#define R_WS   (NPER*1280)
#define R_US   (NPER*256)          // 16 n x 32 bb x 8
#define R_EX   (2*NCAPS*32)
#define R_SMEM ((R_WS + R_US + R_EX)*4)

__global__ __launch_bounds__(320) void route_kernel(
    const float* __restrict__ W, int iter)
{
    extern __shared__ float dsm[];
    float* Ws = dsm;                 // [16][1280]
    float* us = dsm + R_WS;          // [16][32][8]
    float* ex = dsm + R_WS + R_US;   // [2][10][32]

    int tid  = threadIdx.x;          // 0..319
    int o    = tid >> 5;             // warp = capsule o
    int lane = tid & 31;
    int h    = blockIdx.y;           // bb half
    int bb   = h*32 + lane;
    int n0   = blockIdx.x * NPER;

    u32 s_ws = (u32)__cvta_generic_to_shared(Ws);
    u32 s_us = (u32)__cvta_generic_to_shared(us);

    // stage all W: 5120 chunks = exactly 16 * 320
    const float* wsrc = W + (size_t)n0*1280;
#pragma unroll
    for (int k = 0; k < 16; k++) {
        int i = tid + k*320;
        cpasync16(s_ws + i*16, wsrc + (size_t)i*4);
    }
    // stage all u for this bb-half: 1024 chunks
#pragma unroll
    for (int k = 0; k < 4; k++) {
        int i = tid + k*320;
        if (i < 1024) {
            int nn = i >> 6, idx = i & 63;
            const float* usrc = g_u + ((size_t)(n0+nn)*BATCH + h*32)*JDIM + idx*4;
            cpasync16(s_us + i*16, usrc);
        }
    }
    cpcommit();

    float v[16];
    if (iter > 0) {
        const float4* vp = (const float4*)(g_v + (bb*NCAPS + o)*ODIM);
#pragma unroll
        for (int k = 0; k < 4; k++) {
            float4 f = vp[k];
            v[4*k] = f.x; v[4*k+1] = f.y; v[4*k+2] = f.z; v[4*k+3] = f.w;
        }
    }

    float acc[16];
#pragma unroll
    for (int i = 0; i < 16; i++) acc[i] = 0.f;

    cpwait0();
    __syncthreads();

    for (int nn = 0; nn < NPER; nn++) {
        const float4* up = (const float4*)(us + (nn*32 + lane)*JDIM);
        float4 ua = up[0], ub = up[1];

        float uh[16];
        const float* wrow = Ws + nn*1280 + o*128;   // warp-uniform -> broadcast
#pragma unroll
        for (int i = 0; i < 16; i++) {
            float4 wa = *(const float4*)(wrow + i*8);
            float4 wb = *(const float4*)(wrow + i*8 + 4);
            float s = wa.x * ua.x;
            s = fmaf(wa.y, ua.y, s); s = fmaf(wa.z, ua.z, s); s = fmaf(wa.w, ua.w, s);
            s = fmaf(wb.x, ub.x, s); s = fmaf(wb.y, ub.y, s);
            s = fmaf(wb.z, ub.z, s); s = fmaf(wb.w, ub.w, s);
            uh[i] = s;
        }

        float c;
        if (iter == 0) {
            c = 0.1f;
        } else {
            float bnew = 0.f;
#pragma unroll
            for (int i = 0; i < 16; i++) bnew = fmaf(uh[i], v[i], bnew);
            float e = __expf(bnew);
            int par = nn & 1;
            ex[(par*NCAPS + o)*32 + lane] = e;
            __syncthreads();            // also protects ex reuse (parity dbl-buf)
            float denom = 0.f;
#pragma unroll
            for (int k = 0; k < 10; k++) denom += ex[(par*NCAPS + k)*32 + lane];
            c = __fdividef(e, denom);
        }
#pragma unroll
        for (int i = 0; i < 16; i++) acc[i] = fmaf(c, uh[i], acc[i]);
    }

    int rep = (blockIdx.x*2 + blockIdx.y) & (NREP-1);
    float* sp = g_sR + rep*(BATCH*NCAPS*ODIM) + (bb*NCAPS + o)*ODIM;
#pragma unroll
    for (int i = 0; i < 16; i++) atomicAdd(&sp[i], acc[i]);
}

// ============================================================
// sum 8 replicas, squash -> v / out; re-zero replicas.
// mode 0: g_v = v0 ; mode 1: g_v += v1 ; mode 2: write out
// ============================================================
__global__ __launch_bounds__(256) void squash_v_kernel(float* __restrict__ out, int mode)
{
    int tid  = blockIdx.x*256 + threadIdx.x;
    int boq  = tid >> 2;
    int quad = tid & 3;

    float4 s = make_float4(0.f, 0.f, 0.f, 0.f);
#pragma unroll
    for (int r = 0; r < NREP; r++) {
        float* p = g_sR + r*(BATCH*NCAPS*ODIM) + boq*ODIM + quad*4;
        float4 t = *(const float4*)p;
        *(float4*)p = make_float4(0.f, 0.f, 0.f, 0.f);
        s.x += t.x; s.y += t.y; s.z += t.z; s.w += t.w;
    }

    float part = s.x*s.x + s.y*s.y + s.z*s.z + s.w*s.w;
    part += __shfl_xor_sync(0xffffffff, part, 1);
    part += __shfl_xor_sync(0xffffffff, part, 2);
    float msq   = part;
    float mag   = sqrtf(msq + EPS);
    float scale = msq / (1.f + msq) / (mag + EPS);
    float4 vv = make_float4(s.x*scale, s.y*scale, s.z*scale, s.w*scale);

    if (mode == 0) {
        *(float4*)(g_v + boq*ODIM + quad*4) = vv;
    } else if (mode == 1) {
        float4 old = *(const float4*)(g_v + boq*ODIM + quad*4);
        old.x += vv.x; old.y += vv.y; old.z += vv.z; old.w += vv.w;
        *(float4*)(g_v + boq*ODIM + quad*4) = old;
    } else {
        *(float4*)(out + boq*ODIM + quad*4) = vv;
    }
}

// ============================================================
extern "C" void kernel_launch(void* const* d_in, const int* in_sizes, int n_in,
                              void* d_out, int out_size)
{
    const float* x   = (const float*)d_in[0];
    const float* c1w = (const float*)d_in[1];
    const float* c1b = (const float*)d_in[2];
    const float* pw  = (const float*)d_in[3];
    const float* pb  = (const float*)d_in[4];
    const float* W   = (const float*)d_in[5];
    float* out = (float*)d_out;

    static int attr_done = 0;
    if (!attr_done) {
        cudaFuncSetAttribute(conv2_kernel, cudaFuncAttributeMaxDynamicSharedMemorySize, C2_SMEM);
        cudaFuncSetAttribute(route_kernel, cudaFuncAttributeMaxDynamicSharedMemorySize, R_SMEM);
        attr_done = 1;
    }

    w_transform_kernel<<<(64*64*81 + 255)/256, 256>>>(pw);
    conv1_kernel<<<dim3(4,4,64), dim3(16,16)>>>(x, c1w, c1b);
    conv2_kernel<<<dim3(7,64), 224, C2_SMEM>>>(pb);

    route_kernel<<<dim3(392,2), 320, R_SMEM>>>(W, 0);
    squash_v_kernel<<<10, 256>>>(out, 0);
    route_kernel<<<dim3(392,2), 320, R_SMEM>>>(W, 1);
    squash_v_kernel<<<10, 256>>>(out, 1);
    route_kernel<<<dim3(392,2), 320, R_SMEM>>>(W, 2);
    squash_v_kernel<<<10, 256>>>(out, 2);
}